// round 14
// baseline (speedup 1.0000x reference)
#include <cuda_runtime.h>
#include <cuda_fp16.h>

#define NF    40
#define DIM   64
#define AD    32
#define NP    780
#define NPAD  784         // 49 * 16
#define XSTRH 72          // halves; 144B row stride
#define BLK   128
#define NWARP (BLK / 32)
#define NTILE 49
#define NTPAD 53          // NTILE + NWARP (prefetch padding)
#define OCC   4
#define GRID  (148 * OCC)

__device__ __forceinline__ unsigned h2u(__half2 h) {
    return *reinterpret_cast<unsigned*>(&h);
}

__device__ __forceinline__ void mma_f16(float* acc,
                                        unsigned a0, unsigned a1, unsigned a2, unsigned a3,
                                        unsigned b0, unsigned b1) {
    asm("mma.sync.aligned.m16n8k16.row.col.f32.f16.f16.f32 "
        "{%0,%1,%2,%3}, {%4,%5,%6,%7}, {%8,%9}, {%0,%1,%2,%3};"
        : "+f"(acc[0]), "+f"(acc[1]), "+f"(acc[2]), "+f"(acc[3])
        : "r"(a0), "r"(a1), "r"(a2), "r"(a3), "r"(b0), "r"(b1));
}

// NOT volatile: let ptxas schedule LDSMs across the MMA stream
__device__ __forceinline__ void ldsm_x4(unsigned* r, unsigned addr) {
    asm("ldmatrix.sync.aligned.m8n8.x4.shared.b16 {%0,%1,%2,%3}, [%4];"
        : "=r"(r[0]), "=r"(r[1]), "=r"(r[2]), "=r"(r[3]) : "r"(addr));
}

__global__ __launch_bounds__(BLK, OCC)
void afm_kernel(const float* __restrict__ inputs,   // [B, 40, 64]
                const float* __restrict__ W1,       // [64, 32]
                const float* __restrict__ b1,       // [32]
                const float* __restrict__ w2,       // [32]
                const float* __restrict__ pvec,     // [64]
                float* __restrict__ out,            // [B]
                int B)
{
    __shared__ __align__(16) __half xs[NF * XSTRH];
    __shared__ __align__(16) float lsm4[NPAD][4];     // per-q partial logits
    __shared__ float csm[NPAD];
    __shared__ float red[2 * NWARP + 2];
    __shared__ unsigned short pridx[NP];
    __shared__ uint2 atab[NTPAD][32];                 // per-(tile,lane) smem byte offsets

    const int t    = threadIdx.x;
    const int lane = t & 31;
    const int w    = t >> 5;
    const int q    = lane & 3;
    const int g    = lane >> 2;

    // ================= one-time init (per persistent CTA) =================
    if (t < NF - 1) {
        int i = t;
        int base = i * (2 * NF - 1 - i) / 2;
        for (int j = i + 1; j < NF; j++)
            pridx[base + (j - i - 1)] = (unsigned short)((i << 8) | j);
    }

    // B fragments: W1 (nt 0..3) + [p_hi, p_lo, 0...] (nt 4)
    unsigned bh[4][5][2];
    #pragma unroll
    for (int kt = 0; kt < 4; kt++)
        #pragma unroll
        for (int r = 0; r < 2; r++) {
            const int k0 = kt * 16 + 2 * q + 8 * r;
            #pragma unroll
            for (int nt = 0; nt < 4; nt++) {
                const int n = nt * 8 + g;
                bh[kt][nt][r] = h2u(__floats2half2_rn(W1[k0 * AD + n],
                                                      W1[(k0 + 1) * AD + n]));
            }
            float p0 = pvec[k0], p1 = pvec[k0 + 1];
            __half2 phi = __floats2half2_rn(p0, p1);
            float2 pf = __half22float2(phi);
            __half2 plo = __floats2half2_rn(p0 - pf.x, p1 - pf.y);
            unsigned bv = 0;
            if (g == 0) bv = h2u(phi);
            else if (g == 1) bv = h2u(plo);
            bh[kt][4][r] = bv;
        }
    float4 bw[4];
    #pragma unroll
    for (int nt = 0; nt < 4; nt++) {
        const int cc0 = nt * 8 + 2 * q;
        bw[nt] = make_float4(b1[cc0], b1[cc0 + 1], w2[cc0], w2[cc0 + 1]);
    }
    __syncthreads();   // pridx ready

    // precompute LDSM addresses (padded for prefetch): atab[tile][lane]
    for (int idx = t; idx < NTPAD * 32; idx += BLK) {
        int tile = idx >> 5, ln = idx & 31;
        int pl = tile * 16 + (ln & 15);
        pl = pl < NP ? pl : NP - 1;
        unsigned pp = pridx[pl];
        unsigned koff = (unsigned)(ln >> 4) << 3;
        atab[tile][ln] = make_uint2(2u * ((pp >> 8) * XSTRH + koff),
                                    2u * ((pp & 255u) * XSTRH + koff));
    }
    const unsigned xs_base = (unsigned)__cvta_generic_to_shared(xs);

    // ================= persistent batch loop =================
    for (int bi = blockIdx.x; bi < B; bi += GRID) {
        __syncthreads();   // prev softmax reads done before xs/lsm4 overwrite

        // ---- load + convert this batch row ----
        const float* xin = inputs + (size_t)bi * (NF * DIM);
        #pragma unroll
        for (int idx = t; idx < NF * 16; idx += BLK) {
            int r = idx >> 4, c4 = (idx & 15) << 2;
            float4 v = *(const float4*)(xin + r * 64 + c4);
            *(__half2*)(xs + r * XSTRH + c4)     = __floats2half2_rn(v.x, v.y);
            *(__half2*)(xs + r * XSTRH + c4 + 2) = __floats2half2_rn(v.z, v.w);
        }
        __syncthreads();

        // ---- mainloop: kt-pipeline carried ACROSS tile boundaries ----
        uint2 ao = atab[w][lane];
        unsigned xi_addr = xs_base + ao.x;
        unsigned xj_addr = xs_base + ao.y;
        unsigned xi[2][4], xj[2][4];
        ldsm_x4(xi[0], xi_addr);          // tile w, kt0
        ldsm_x4(xj[0], xj_addr);

        for (int tile = w; tile < NTILE; tile += NWARP) {
            const uint2 ao_n = atab[tile + NWARP][lane];   // padded, always valid
            const unsigned xi_addr_n = xs_base + ao_n.x;
            const unsigned xj_addr_n = xs_base + ao_n.y;

            // acc init: b1 folded in (nt 0..3); cp rows (nt 4) start at 0
            float acc[5][4];
            #pragma unroll
            for (int nt = 0; nt < 4; nt++) {
                acc[nt][0] = bw[nt].x; acc[nt][1] = bw[nt].y;
                acc[nt][2] = bw[nt].x; acc[nt][3] = bw[nt].y;
            }
            acc[4][0] = acc[4][1] = acc[4][2] = acc[4][3] = 0.f;

            #pragma unroll
            for (int kt = 0; kt < 4; kt++) {
                const int cur = kt & 1, nxt = cur ^ 1;
                if (kt < 3) {
                    ldsm_x4(xi[nxt], xi_addr + (kt + 1) * 32);
                    ldsm_x4(xj[nxt], xj_addr + (kt + 1) * 32);
                } else {
                    // prefetch NEXT tile's kt0 — in flight during the epilogue
                    ldsm_x4(xi[nxt], xi_addr_n);
                    ldsm_x4(xj[nxt], xj_addr_n);
                }
                unsigned ah0 = h2u(__hmul2(*(__half2*)&xi[cur][0], *(__half2*)&xj[cur][0]));
                unsigned ah1 = h2u(__hmul2(*(__half2*)&xi[cur][1], *(__half2*)&xj[cur][1]));
                unsigned ah2 = h2u(__hmul2(*(__half2*)&xi[cur][2], *(__half2*)&xj[cur][2]));
                unsigned ah3 = h2u(__hmul2(*(__half2*)&xi[cur][3], *(__half2*)&xj[cur][3]));

                #pragma unroll
                for (int nt = 0; nt < 5; nt++)
                    mma_f16(acc[nt], ah0, ah1, ah2, ah3, bh[kt][nt][0], bh[kt][nt][1]);
            }

            // epilogue: per-q partial of relu(h) . w2 (overlaps next tile's kt0 LDSM)
            float s0 = 0.f, s1 = 0.f;
            #pragma unroll
            for (int nt = 0; nt < 4; nt++) {
                float4 c = bw[nt];
                s0 = fmaf(fmaxf(acc[nt][0], 0.f), c.z, s0);
                s0 = fmaf(fmaxf(acc[nt][1], 0.f), c.w, s0);
                s1 = fmaf(fmaxf(acc[nt][2], 0.f), c.z, s1);
                s1 = fmaf(fmaxf(acc[nt][3], 0.f), c.w, s1);
            }
            const int rowA = tile * 16 + g;
            const int rowB = rowA + 8;
            lsm4[rowA][q] = s0;
            lsm4[rowB][q] = s1;
            if (q == 0) {
                csm[rowA] = acc[4][0] + acc[4][1];
                csm[rowB] = acc[4][2] + acc[4][3];
            }
            ao = ao_n;
            xi_addr = xi_addr_n;
            xj_addr = xj_addr_n;
            // note: xi[0]/xj[0] now hold next tile's kt0 (4 kt = even count, buffer parity works out)
        }
        __syncthreads();

        // ---- one-pass softmax (no max shift; logits are O(1)) ----
        float s = 0.f, ws = 0.f;
        #pragma unroll
        for (int p0 = t; p0 < NP; p0 += BLK) {
            float4 v = *(const float4*)lsm4[p0];
            float e = __expf((v.x + v.y) + (v.z + v.w));
            s += e;
            ws = fmaf(e, csm[p0], ws);
        }
        #pragma unroll
        for (int o = 16; o; o >>= 1) {
            s  += __shfl_xor_sync(0xffffffffu, s, o);
            ws += __shfl_xor_sync(0xffffffffu, ws, o);
        }
        if (lane == 0) { red[w] = s; red[NWARP + w] = ws; }
        __syncthreads();
        if (t == 0) {
            float S = 0.f, WS = 0.f;
            #pragma unroll
            for (int ww = 0; ww < NWARP; ww++) { S += red[ww]; WS += red[NWARP + ww]; }
            out[bi] = WS / S;
        }
    }
}

extern "C" void kernel_launch(void* const* d_in, const int* in_sizes, int n_in,
                              void* d_out, int out_size)
{
    const float* inputs = (const float*)d_in[0];
    const float* W1     = (const float*)d_in[1];
    const float* b1     = (const float*)d_in[2];
    const float* w2     = (const float*)d_in[3];
    const float* pvec   = (const float*)d_in[4];
    float* out = (float*)d_out;

    int B = in_sizes[0] / (NF * DIM);   // 8192
    int grid = B < GRID ? B : GRID;
    afm_kernel<<<grid, BLK>>>(inputs, W1, b1, w2, pvec, out, B);
}

// round 15
// speedup vs baseline: 1.0123x; 1.0123x over previous
#include <cuda_runtime.h>
#include <cuda_fp16.h>

#define NF    40
#define DIM   64
#define AD    32
#define NP    780
#define NPAD  784         // 49 * 16
#define XSTRH 72          // halves; 144B row stride
#define BLK   128
#define NWARP (BLK / 32)
#define NTILE 49
#define OCC   3
#define GRID  (148 * OCC)

__device__ __forceinline__ unsigned h2u(__half2 h) {
    return *reinterpret_cast<unsigned*>(&h);
}

__device__ __forceinline__ void mma_f16(float* acc,
                                        unsigned a0, unsigned a1, unsigned a2, unsigned a3,
                                        unsigned b0, unsigned b1) {
    asm("mma.sync.aligned.m16n8k16.row.col.f32.f16.f16.f32 "
        "{%0,%1,%2,%3}, {%4,%5,%6,%7}, {%8,%9}, {%0,%1,%2,%3};"
        : "+f"(acc[0]), "+f"(acc[1]), "+f"(acc[2]), "+f"(acc[3])
        : "r"(a0), "r"(a1), "r"(a2), "r"(a3), "r"(b0), "r"(b1));
}

// NOT volatile: let ptxas schedule LDSMs freely
__device__ __forceinline__ void ldsm_x4(unsigned* r, unsigned addr) {
    asm("ldmatrix.sync.aligned.m8n8.x4.shared.b16 {%0,%1,%2,%3}, [%4];"
        : "=r"(r[0]), "=r"(r[1]), "=r"(r[2]), "=r"(r[3]) : "r"(addr));
}

__global__ __launch_bounds__(BLK, OCC)
void afm_kernel(const float* __restrict__ inputs,   // [B, 40, 64]
                const float* __restrict__ W1,       // [64, 32]
                const float* __restrict__ b1,       // [32]
                const float* __restrict__ w2,       // [32]
                const float* __restrict__ pvec,     // [64]
                float* __restrict__ out,            // [B]
                int B)
{
    __shared__ __align__(16) __half xs[NF * XSTRH];
    __shared__ __align__(16) float lsm4[NPAD][4];     // per-q partial logits
    __shared__ float csm[NPAD];
    __shared__ float red[2 * NWARP + 2];
    __shared__ unsigned short pridx[NP];
    __shared__ uint2 atab[NTILE][32];                 // per-(tile,lane) smem byte offsets

    const int t    = threadIdx.x;
    const int lane = t & 31;
    const int w    = t >> 5;
    const int q    = lane & 3;
    const int g    = lane >> 2;

    // ================= one-time init (per persistent CTA) =================
    if (t < NF - 1) {
        int i = t;
        int base = i * (2 * NF - 1 - i) / 2;
        for (int j = i + 1; j < NF; j++)
            pridx[base + (j - i - 1)] = (unsigned short)((i << 8) | j);
    }

    // B fragments: W1 (nt 0..3) + [p_hi, p_lo, 0...] (nt 4)
    unsigned bh[4][5][2];
    #pragma unroll
    for (int kt = 0; kt < 4; kt++)
        #pragma unroll
        for (int r = 0; r < 2; r++) {
            const int k0 = kt * 16 + 2 * q + 8 * r;
            #pragma unroll
            for (int nt = 0; nt < 4; nt++) {
                const int n = nt * 8 + g;
                bh[kt][nt][r] = h2u(__floats2half2_rn(W1[k0 * AD + n],
                                                      W1[(k0 + 1) * AD + n]));
            }
            float p0 = pvec[k0], p1 = pvec[k0 + 1];
            __half2 phi = __floats2half2_rn(p0, p1);
            float2 pf = __half22float2(phi);
            __half2 plo = __floats2half2_rn(p0 - pf.x, p1 - pf.y);
            unsigned bv = 0;
            if (g == 0) bv = h2u(phi);
            else if (g == 1) bv = h2u(plo);
            bh[kt][4][r] = bv;
        }
    float4 bw[4];
    #pragma unroll
    for (int nt = 0; nt < 4; nt++) {
        const int cc0 = nt * 8 + 2 * q;
        bw[nt] = make_float4(b1[cc0], b1[cc0 + 1], w2[cc0], w2[cc0 + 1]);
    }
    __syncthreads();   // pridx ready

    // precompute LDSM addresses: atab[tile][lane]
    for (int idx = t; idx < NTILE * 32; idx += BLK) {
        int tile = idx >> 5, ln = idx & 31;
        int pl = tile * 16 + (ln & 15);
        pl = pl < NP ? pl : NP - 1;
        unsigned pp = pridx[pl];
        unsigned koff = (unsigned)(ln >> 4) << 3;
        atab[tile][ln] = make_uint2(2u * ((pp >> 8) * XSTRH + koff),
                                    2u * ((pp & 255u) * XSTRH + koff));
    }
    const unsigned xs_base = (unsigned)__cvta_generic_to_shared(xs);

    // ================= persistent batch loop =================
    for (int bi = blockIdx.x; bi < B; bi += GRID) {
        __syncthreads();   // prev softmax reads done before xs/lsm4 overwrite

        // ---- load + convert this batch row ----
        const float* xin = inputs + (size_t)bi * (NF * DIM);
        #pragma unroll
        for (int idx = t; idx < NF * 16; idx += BLK) {
            int r = idx >> 4, c4 = (idx & 15) << 2;
            float4 v = *(const float4*)(xin + r * 64 + c4);
            *(__half2*)(xs + r * XSTRH + c4)     = __floats2half2_rn(v.x, v.y);
            *(__half2*)(xs + r * XSTRH + c4 + 2) = __floats2half2_rn(v.z, v.w);
        }
        __syncthreads();

        // ---- mainloop: load whole tile's fragments, then compute ----
        for (int tile = w; tile < NTILE; tile += NWARP) {
            const uint2 ao = atab[tile][lane];
            const unsigned xi_addr = xs_base + ao.x;
            const unsigned xj_addr = xs_base + ao.y;

            // all 8 LDSM.x4 back-to-back: latencies fully overlapped
            unsigned xi[4][4], xj[4][4];
            #pragma unroll
            for (int kt = 0; kt < 4; kt++) {
                ldsm_x4(xi[kt], xi_addr + kt * 32);
                ldsm_x4(xj[kt], xj_addr + kt * 32);
            }

            // acc init: b1 folded in (nt 0..3); cp rows (nt 4) start at 0
            float acc[5][4];
            #pragma unroll
            for (int nt = 0; nt < 4; nt++) {
                acc[nt][0] = bw[nt].x; acc[nt][1] = bw[nt].y;
                acc[nt][2] = bw[nt].x; acc[nt][3] = bw[nt].y;
            }
            acc[4][0] = acc[4][1] = acc[4][2] = acc[4][3] = 0.f;

            #pragma unroll
            for (int kt = 0; kt < 4; kt++) {
                unsigned ah0 = h2u(__hmul2(*(__half2*)&xi[kt][0], *(__half2*)&xj[kt][0]));
                unsigned ah1 = h2u(__hmul2(*(__half2*)&xi[kt][1], *(__half2*)&xj[kt][1]));
                unsigned ah2 = h2u(__hmul2(*(__half2*)&xi[kt][2], *(__half2*)&xj[kt][2]));
                unsigned ah3 = h2u(__hmul2(*(__half2*)&xi[kt][3], *(__half2*)&xj[kt][3]));

                #pragma unroll
                for (int nt = 0; nt < 5; nt++)
                    mma_f16(acc[nt], ah0, ah1, ah2, ah3, bh[kt][nt][0], bh[kt][nt][1]);
            }

            // epilogue: per-q partial of relu(h) . w2
            float s0 = 0.f, s1 = 0.f;
            #pragma unroll
            for (int nt = 0; nt < 4; nt++) {
                float4 c = bw[nt];
                s0 = fmaf(fmaxf(acc[nt][0], 0.f), c.z, s0);
                s0 = fmaf(fmaxf(acc[nt][1], 0.f), c.w, s0);
                s1 = fmaf(fmaxf(acc[nt][2], 0.f), c.z, s1);
                s1 = fmaf(fmaxf(acc[nt][3], 0.f), c.w, s1);
            }
            const int rowA = tile * 16 + g;
            const int rowB = rowA + 8;
            lsm4[rowA][q] = s0;
            lsm4[rowB][q] = s1;
            if (q == 0) {
                csm[rowA] = acc[4][0] + acc[4][1];
                csm[rowB] = acc[4][2] + acc[4][3];
            }
        }
        __syncthreads();

        // ---- one-pass softmax (no max shift; logits are O(1)) ----
        float s = 0.f, ws = 0.f;
        #pragma unroll
        for (int p0 = t; p0 < NP; p0 += BLK) {
            float4 v = *(const float4*)lsm4[p0];
            float e = __expf((v.x + v.y) + (v.z + v.w));
            s += e;
            ws = fmaf(e, csm[p0], ws);
        }
        #pragma unroll
        for (int o = 16; o; o >>= 1) {
            s  += __shfl_xor_sync(0xffffffffu, s, o);
            ws += __shfl_xor_sync(0xffffffffu, ws, o);
        }
        if (lane == 0) { red[w] = s; red[NWARP + w] = ws; }
        __syncthreads();
        if (t == 0) {
            float S = 0.f, WS = 0.f;
            #pragma unroll
            for (int ww = 0; ww < NWARP; ww++) { S += red[ww]; WS += red[NWARP + ww]; }
            out[bi] = WS / S;
        }
    }
}

extern "C" void kernel_launch(void* const* d_in, const int* in_sizes, int n_in,
                              void* d_out, int out_size)
{
    const float* inputs = (const float*)d_in[0];
    const float* W1     = (const float*)d_in[1];
    const float* b1     = (const float*)d_in[2];
    const float* w2     = (const float*)d_in[3];
    const float* pvec   = (const float*)d_in[4];
    float* out = (float*)d_out;

    int B = in_sizes[0] / (NF * DIM);   // 8192
    int grid = B < GRID ? B : GRID;
    afm_kernel<<<grid, BLK>>>(inputs, W1, b1, w2, pvec, out, B);
}